// round 5
// baseline (speedup 1.0000x reference)
#include <cuda_runtime.h>
#include <math.h>

#define BATCH 32

// scratch (device globals: sanctioned workaround for no-alloc rule)
__device__ float g_a1[32 * 64 * 126 * 126];
__device__ float g_p1[32 * 64 * 62 * 62];
__device__ float g_a2[32 * 64 * 60 * 60];
__device__ float g_p2[32 * 64 * 29 * 29];
__device__ float g_a3[32 * 64 * 27 * 27];
__device__ float g_p3[32 * 64 * 13 * 13];
__device__ float g_U1[64 * 16 * 64];   // winograd weights [cin][xi][cout]
__device__ float g_U2[64 * 16 * 64];
__device__ float g_U3[64 * 16 * 64];
__device__ double g_dsum[64];
__device__ double g_dsq[64];
__device__ double g_xs[9];
__device__ float g_scale[4][64];
__device__ float g_bias[4][64];
__device__ float g_traw[32 * 6];
__device__ float g_theta[32 * 6];

// ---------------------------------------------------------------------------
__global__ void zero_stats_kernel() {
    int t = threadIdx.x;
    if (t < 64) { g_dsum[t] = 0.0; g_dsq[t] = 0.0; }
    if (t < 9)  { g_xs[t] = 0.0; }
}

__global__ void statsx_kernel(const float* __restrict__ x) {
    __shared__ float red[256];
    float a[9];
#pragma unroll
    for (int i = 0; i < 9; i++) a[i] = 0.f;
    for (int idx = blockIdx.x * 256 + threadIdx.x; idx < BATCH * 16384;
         idx += gridDim.x * 256) {
        int b = idx >> 14, p = idx & 16383;
        float x0 = x[(b * 3 + 0) * 16384 + p];
        float x1 = x[(b * 3 + 1) * 16384 + p];
        float x2 = x[(b * 3 + 2) * 16384 + p];
        a[0] = fmaf(x0, x0, a[0]); a[1] = fmaf(x0, x1, a[1]);
        a[2] = fmaf(x0, x2, a[2]); a[3] = fmaf(x1, x1, a[3]);
        a[4] = fmaf(x1, x2, a[4]); a[5] = fmaf(x2, x2, a[5]);
        a[6] += x0; a[7] += x1; a[8] += x2;
    }
#pragma unroll
    for (int q = 0; q < 9; q++) {
        red[threadIdx.x] = a[q];
        __syncthreads();
        for (int o = 128; o > 0; o >>= 1) {
            if (threadIdx.x < o) red[threadIdx.x] += red[threadIdx.x + o];
            __syncthreads();
        }
        if (threadIdx.x == 0) atomicAdd(&g_xs[q], (double)red[0]);
        __syncthreads();
    }
}

__global__ void scalebias0_kernel(const float* __restrict__ w0,
                                  const float* __restrict__ gamma,
                                  const float* __restrict__ beta) {
    int o = threadIdx.x;
    if (o >= 64) return;
    const double N = 524288.0;
    double C00 = g_xs[0] / N, C01 = g_xs[1] / N, C02 = g_xs[2] / N;
    double C11 = g_xs[3] / N, C12 = g_xs[4] / N, C22 = g_xs[5] / N;
    double m0 = g_xs[6] / N, m1 = g_xs[7] / N, m2 = g_xs[8] / N;
    double w0v = w0[o * 3 + 0], w1v = w0[o * 3 + 1], w2v = w0[o * 3 + 2];
    double m = w0v * m0 + w1v * m1 + w2v * m2;
    double e2 = w0v * w0v * C00 + w1v * w1v * C11 + w2v * w2v * C22 +
                2.0 * (w0v * w1v * C01 + w0v * w2v * C02 + w1v * w2v * C12);
    double var = e2 - m * m;
    double sc = (double)gamma[o] / sqrt(var + 1e-5);
    g_scale[0][o] = (float)sc;
    g_bias[0][o] = (float)((double)beta[o] - m * sc);
}

__global__ void scalebias_kernel(int l, const float* __restrict__ gamma,
                                 const float* __restrict__ beta, double N) {
    int c = threadIdx.x;
    if (c >= 64) return;
    double m = g_dsum[c] / N;
    double var = g_dsq[c] / N - m * m;
    double sc = (double)gamma[c] / sqrt(var + 1e-5);
    g_scale[l][c] = (float)sc;
    g_bias[l][c] = (float)((double)beta[c] - m * sc);
    g_dsum[c] = 0.0;
    g_dsq[c] = 0.0;
}

// ---------------------------------------------------------------------------
// winograd weight transform for w1/w2/w3: U = G g G^T, stored [cin][xi][cout]
__global__ void uweights_kernel(const float* __restrict__ w1,
                                const float* __restrict__ w2,
                                const float* __restrict__ w3) {
    const float* w = (blockIdx.y == 0) ? w1 : (blockIdx.y == 1) ? w2 : w3;
    float* gU = (blockIdx.y == 0) ? g_U1 : (blockIdx.y == 1) ? g_U2 : g_U3;
    int cin = blockIdx.x;
    int cout = threadIdx.x;
    float g[9];
#pragma unroll
    for (int t = 0; t < 9; t++) g[t] = w[(cout * 64 + cin) * 9 + t];
    float T[4][3];
#pragma unroll
    for (int c = 0; c < 3; c++) {
        T[0][c] = g[0 * 3 + c];
        T[1][c] = 0.5f * (g[0 * 3 + c] + g[1 * 3 + c] + g[2 * 3 + c]);
        T[2][c] = 0.5f * (g[0 * 3 + c] - g[1 * 3 + c] + g[2 * 3 + c]);
        T[3][c] = g[2 * 3 + c];
    }
#pragma unroll
    for (int r = 0; r < 4; r++) {
        gU[cin * 1024 + (r * 4 + 0) * 64 + cout] = T[r][0];
        gU[cin * 1024 + (r * 4 + 1) * 64 + cout] =
            0.5f * (T[r][0] + T[r][1] + T[r][2]);
        gU[cin * 1024 + (r * 4 + 2) * 64 + cout] =
            0.5f * (T[r][0] - T[r][1] + T[r][2]);
        gU[cin * 1024 + (r * 4 + 3) * 64 + cout] = T[r][2];
    }
}

// ---------------------------------------------------------------------------
// Winograd F(2x2,3x3), GEMM formulation. 512 threads = 16 warps; warp w owns
// xi=w. Block: 16x16 output px (8x8 tiles) x 32 couts (half z). Per warp:
// M[xi][64 tiles][32 couts] via 8x8 outer-product blocking per thread.
// C1: fuse conv0(1x1)+bn0+relu into staging from x.
template <int IH, bool C1>
__global__ __launch_bounds__(512, 1) void winograd_kernel(
    const float* __restrict__ src, const float* __restrict__ w0,
    const float* __restrict__ gU, float* __restrict__ dst, int lidx) {
    constexpr int OH = IH - 2;
    constexpr int TILES = (OH + 1) / 2;
    constexpr int RX = (TILES + 7) / 8;
    __shared__ float xs[C1 ? 3 * 360 : 4];
    __shared__ union SMem {
        struct {
            float hs[4][360];
            float Us[4][16][32];
            float Vs[4][16 * 68];  // [ci][xi*68 + tile]
        } a;
        float Ms[16][64][9];       // [xi][tile][cout-in-chunk] (padded)
    } sm;

    const int b = blockIdx.y;
    const int z = blockIdx.z;
    const int rgx = blockIdx.x % RX, rgy = blockIdx.x / RX;
    const int ry0 = rgy * 16, rx0 = rgx * 16;
    const int tid = threadIdx.x;
    const int w = tid >> 5;          // warp = xi
    const int lane = tid & 31;
    const int tg = lane >> 2;        // tile group (8 tiles)
    const int cq = lane & 3;         // cout group (8 couts)
    const int tile = tid >> 3;       // for transform stage: 0..63
    const int cg = tid & 7;
    const int ty = tile >> 3, tx = tile & 7;

    if (C1) {
        for (int idx = tid; idx < 3 * 324; idx += 512) {
            int c = idx / 324, p = idx - c * 324;
            int iy = p / 18, ix = p - iy * 18;
            int gy = ry0 + iy, gx = rx0 + ix;
            float v = 0.f;
            if (gy < IH && gx < IH) v = src[((b * 3 + c) * IH + gy) * IH + gx];
            xs[c * 360 + iy * 20 + ix] = v;
        }
    }

    float acc[8][8];
#pragma unroll
    for (int i = 0; i < 8; i++)
#pragma unroll
        for (int j = 0; j < 8; j++) acc[i][j] = 0.f;

    for (int cc = 0; cc < 16; cc++) {
        const int cin0 = cc * 4;
        __syncthreads();
        // stage hs (bn+relu; C1: conv0 first) and Us
        for (int idx = tid; idx < 4 * 324; idx += 512) {
            int ci = idx / 324, p = idx - ci * 324;
            int iy = p / 18, ix = p - iy * 18;
            int o = iy * 20 + ix;
            int cin = cin0 + ci;
            float v;
            if (C1) {
                v = xs[o] * w0[cin * 3] + xs[360 + o] * w0[cin * 3 + 1] +
                    xs[720 + o] * w0[cin * 3 + 2];
            } else {
                int gy = ry0 + iy, gx = rx0 + ix;
                v = 0.f;
                if (gy < IH && gx < IH)
                    v = src[((size_t)(b * 64 + cin)) * IH * IH + gy * IH + gx];
            }
            sm.a.hs[ci][o] =
                fmaxf(fmaf(v, g_scale[lidx][cin], g_bias[lidx][cin]), 0.f);
        }
        for (int idx = tid; idx < 2048; idx += 512) {
            int ci = idx >> 9, r = idx & 511;
            int xi = r >> 5, c = r & 31;
            sm.a.Us[ci][xi][c] = gU[(cin0 + ci) * 1024 + xi * 64 + z * 32 + c];
        }
        __syncthreads();
        // input transform: thread (tile, cg) -> xi = 2cg, 2cg+1 per ci
        {
            const int base = (ty * 2) * 20 + tx * 2;
#pragma unroll
            for (int ci = 0; ci < 4; ci++) {
                const float* h = &sm.a.hs[ci][base];
#pragma unroll
                for (int q = 0; q < 2; q++) {
                    int xi = 2 * cg + q;
                    int i = xi >> 2, j = xi & 3;
                    float e0, e1, e2, e3;
                    if (j == 0) {
                        e0 = h[0] - h[2];   e1 = h[20] - h[22];
                        e2 = h[40] - h[42]; e3 = h[60] - h[62];
                    } else if (j == 1) {
                        e0 = h[1] + h[2];   e1 = h[21] + h[22];
                        e2 = h[41] + h[42]; e3 = h[61] + h[62];
                    } else if (j == 2) {
                        e0 = h[2] - h[1];   e1 = h[22] - h[21];
                        e2 = h[42] - h[41]; e3 = h[62] - h[61];
                    } else {
                        e0 = h[1] - h[3];   e1 = h[21] - h[23];
                        e2 = h[41] - h[43]; e3 = h[61] - h[63];
                    }
                    float vv;
                    if (i == 0) vv = e0 - e2;
                    else if (i == 1) vv = e1 + e2;
                    else if (i == 2) vv = e2 - e1;
                    else vv = e1 - e3;
                    sm.a.Vs[ci][xi * 68 + tile] = vv;
                }
            }
        }
        __syncthreads();
        // GEMM: warp w handles xi=w; thread: 8 tiles (tg) x 8 couts (cq)
#pragma unroll
        for (int ci = 0; ci < 4; ci++) {
            const float* vp = &sm.a.Vs[ci][w * 68 + tg * 8];
            float4 va = *(const float4*)(vp);
            float4 vb = *(const float4*)(vp + 4);
            const float* up = &sm.a.Us[ci][w][cq * 8];
            float4 ua = *(const float4*)(up);
            float4 ub = *(const float4*)(up + 4);
            float vv[8] = {va.x, va.y, va.z, va.w, vb.x, vb.y, vb.z, vb.w};
            float uu[8] = {ua.x, ua.y, ua.z, ua.w, ub.x, ub.y, ub.z, ub.w};
#pragma unroll
            for (int t = 0; t < 8; t++)
#pragma unroll
                for (int c = 0; c < 8; c++)
                    acc[t][c] = fmaf(vv[t], uu[c], acc[t][c]);
        }
    }

    // output transform: 4 cout-chunks of 8, gathered across warps via Ms
    for (int k = 0; k < 4; k++) {
        __syncthreads();
        if (cq == k) {
#pragma unroll
            for (int t = 0; t < 8; t++)
#pragma unroll
                for (int c = 0; c < 8; c++)
                    sm.Ms[w][tg * 8 + t][c] = acc[t][c];
        }
        __syncthreads();
        int tile2 = tid >> 3, c2 = tid & 7;
        float m[16];
#pragma unroll
        for (int xi = 0; xi < 16; xi++) m[xi] = sm.Ms[xi][tile2][c2];
        float Z0[4], Z1[4];
#pragma unroll
        for (int j = 0; j < 4; j++) {
            Z0[j] = m[j] + m[4 + j] + m[8 + j];
            Z1[j] = m[4 + j] - m[8 + j] - m[12 + j];
        }
        float y00 = Z0[0] + Z0[1] + Z0[2];
        float y01 = Z0[1] - Z0[2] - Z0[3];
        float y10 = Z1[0] + Z1[1] + Z1[2];
        float y11 = Z1[1] - Z1[2] - Z1[3];
        int cout = z * 32 + k * 8 + c2;
        float* db = dst + ((size_t)(b * 64 + cout)) * OH * OH;
        int oy = ry0 + 2 * (tile2 >> 3), ox = rx0 + 2 * (tile2 & 7);
        if (oy < OH) {
            if (ox < OH) db[oy * OH + ox] = y00;
            if (ox + 1 < OH) db[oy * OH + ox + 1] = y01;
        }
        if (oy + 1 < OH) {
            if (ox < OH) db[(oy + 1) * OH + ox] = y10;
            if (ox + 1 < OH) db[(oy + 1) * OH + ox + 1] = y11;
        }
    }
}

// ---------------------------------------------------------------------------
// fused maxpool(3,2) + per-channel stats
template <int CH, int PH>
__global__ void poolstats_kernel(const float* __restrict__ src,
                                 float* __restrict__ dst) {
    __shared__ float r1[256], r2[256];
    int bc = blockIdx.x;
    int c = bc & 63;
    const float* sb = src + (size_t)bc * CH * CH;
    float* db = dst + (size_t)bc * PH * PH;
    float s = 0.f, q = 0.f;
    for (int i = threadIdx.x; i < PH * PH; i += 256) {
        int py = i / PH, px = i - py * PH;
        const float* w = sb + (2 * py) * CH + 2 * px;
        float m = w[0];
#pragma unroll
        for (int di = 0; di < 3; di++)
#pragma unroll
            for (int dj = 0; dj < 3; dj++) m = fmaxf(m, w[di * CH + dj]);
        db[i] = m;
        s += m;
        q = fmaf(m, m, q);
    }
    r1[threadIdx.x] = s; r2[threadIdx.x] = q;
    __syncthreads();
    for (int o = 128; o > 0; o >>= 1) {
        if (threadIdx.x < o) {
            r1[threadIdx.x] += r1[threadIdx.x + o];
            r2[threadIdx.x] += r2[threadIdx.x + o];
        }
        __syncthreads();
    }
    if (threadIdx.x == 0) {
        atomicAdd(&g_dsum[c], (double)r1[0]);
        atomicAdd(&g_dsq[c], (double)r2[0]);
    }
}

// ---------------------------------------------------------------------------
__global__ void fc_kernel(const float* __restrict__ Wreg,
                          const float* __restrict__ breg) {
    __shared__ float red[256];
    int j = blockIdx.x % 6, b = blockIdx.x / 6;
    const float* pb = g_p3 + (size_t)b * 10816;
    const float* wb = Wreg + (size_t)j * 10816;
    float s = 0.f;
    for (int k = threadIdx.x; k < 10816; k += 256) {
        int c = k / 169;
        float v = fmaxf(fmaf(pb[k], g_scale[3][c], g_bias[3][c]), 0.f);
        s += v * wb[k];
    }
    red[threadIdx.x] = s;
    __syncthreads();
    for (int o = 128; o > 0; o >>= 1) {
        if (threadIdx.x < o) red[threadIdx.x] += red[threadIdx.x + o];
        __syncthreads();
    }
    if (threadIdx.x == 0) g_traw[b * 6 + j] = red[0] + breg[j];
}

__global__ void sn_kernel(const float* __restrict__ u0,
                          const float* __restrict__ v0) {
    if (threadIdx.x != 0 || blockIdx.x != 0) return;
    float u[2] = {u0[0], u0[1]};
    float v[3] = {v0[0], v0[1], v0[2]};
    for (int b = 0; b < 32; b++) {
        float W[6];
#pragma unroll
        for (int i = 0; i < 6; i++) W[i] = g_traw[b * 6 + i];
#pragma unroll
        for (int it = 0; it < 4; it++) {
            float nv[3];
#pragma unroll
            for (int j = 0; j < 3; j++) nv[j] = W[j] * u[0] + W[3 + j] * u[1];
            float n = sqrtf(nv[0] * nv[0] + nv[1] * nv[1] + nv[2] * nv[2]);
            n = fmaxf(n, 1e-12f);
#pragma unroll
            for (int j = 0; j < 3; j++) v[j] = nv[j] / n;
            float nu0 = W[0] * v[0] + W[1] * v[1] + W[2] * v[2];
            float nu1 = W[3] * v[0] + W[4] * v[1] + W[5] * v[2];
            n = sqrtf(nu0 * nu0 + nu1 * nu1);
            n = fmaxf(n, 1e-12f);
            u[0] = nu0 / n; u[1] = nu1 / n;
        }
        float Wv0 = W[0] * v[0] + W[1] * v[1] + W[2] * v[2];
        float Wv1 = W[3] * v[0] + W[4] * v[1] + W[5] * v[2];
        float sigma = u[0] * Wv0 + u[1] * Wv1;
#pragma unroll
        for (int i = 0; i < 6; i++) g_theta[b * 6 + i] = W[i] / sigma;
    }
}

__global__ void sample_kernel(const float* __restrict__ x,
                              float* __restrict__ out) {
    int idx = blockIdx.x * 256 + threadIdx.x;
    if (idx >= BATCH * 16384) return;
    int b = idx >> 14, p = idx & 16383;
    int h = p >> 7, w = p & 127;
    const float* th = &g_theta[b * 6];
    float xsc = (2.f * w + 1.f) / 128.f - 1.f;
    float ysc = (2.f * h + 1.f) / 128.f - 1.f;
    float gx = th[0] * xsc + th[1] * ysc + th[2];
    float gy = th[3] * xsc + th[4] * ysc + th[5];
    float ix = ((gx + 1.f) * 128.f - 1.f) * 0.5f;
    float iy = ((gy + 1.f) * 128.f - 1.f) * 0.5f;
    float r = fmodf(fabsf(ix + 0.5f), 256.f);
    ix = (r > 128.f ? 256.f - r : r) - 0.5f;
    ix = fminf(fmaxf(ix, 0.f), 127.f);
    r = fmodf(fabsf(iy + 0.5f), 256.f);
    iy = (r > 128.f ? 256.f - r : r) - 0.5f;
    iy = fminf(fmaxf(iy, 0.f), 127.f);
    float fx0 = floorf(ix), fy0 = floorf(iy);
    float wx = ix - fx0, wy = iy - fy0;
    int x0 = min(max((int)fx0, 0), 127), y0 = min(max((int)fy0, 0), 127);
    int x1 = min(x0 + 1, 127), y1 = min(y0 + 1, 127);
    float w00 = (1.f - wx) * (1.f - wy), w10 = wx * (1.f - wy);
    float w01 = (1.f - wx) * wy, w11 = wx * wy;
#pragma unroll
    for (int c = 0; c < 3; c++) {
        const float* xb = x + (size_t)(b * 3 + c) * 16384;
        float v = xb[y0 * 128 + x0] * w00 + xb[y0 * 128 + x1] * w10 +
                  xb[y1 * 128 + x0] * w01 + xb[y1 * 128 + x1] * w11;
        out[(size_t)(b * 3 + c) * 16384 + p] = v;
    }
}

// ---------------------------------------------------------------------------
extern "C" void kernel_launch(void* const* d_in, const int* in_sizes, int n_in,
                              void* d_out, int out_size) {
    const float* x     = (const float*)d_in[0];
    const float* w0    = (const float*)d_in[1];
    const float* w1    = (const float*)d_in[2];
    const float* w2    = (const float*)d_in[3];
    const float* w3    = (const float*)d_in[4];
    const float* gamma = (const float*)d_in[5];
    const float* beta  = (const float*)d_in[6];
    const float* Wreg  = (const float*)d_in[7];
    const float* breg  = (const float*)d_in[8];
    const float* u0    = (const float*)d_in[9];
    const float* v0    = (const float*)d_in[10];
    float* out = (float*)d_out;
    (void)n_in; (void)in_sizes; (void)out_size;

    float *pa1, *pp1, *pa2, *pp2, *pa3, *pp3, *pU1, *pU2, *pU3;
    cudaGetSymbolAddress((void**)&pa1, g_a1);
    cudaGetSymbolAddress((void**)&pp1, g_p1);
    cudaGetSymbolAddress((void**)&pa2, g_a2);
    cudaGetSymbolAddress((void**)&pp2, g_p2);
    cudaGetSymbolAddress((void**)&pa3, g_a3);
    cudaGetSymbolAddress((void**)&pp3, g_p3);
    cudaGetSymbolAddress((void**)&pU1, g_U1);
    cudaGetSymbolAddress((void**)&pU2, g_U2);
    cudaGetSymbolAddress((void**)&pU3, g_U3);

    zero_stats_kernel<<<1, 256>>>();
    statsx_kernel<<<512, 256>>>(x);
    uweights_kernel<<<dim3(64, 3), 64>>>(w1, w2, w3);
    scalebias0_kernel<<<1, 64>>>(w0, gamma, beta);

    // conv1 (winograd, fused conv0+bn0+relu) -> pool+stats -> bn1
    winograd_kernel<128, true><<<dim3(64, 32, 2), 512>>>(x, w0, pU1, pa1, 0);
    poolstats_kernel<126, 62><<<2048, 256>>>(pa1, pp1);
    scalebias_kernel<<<1, 64>>>(1, gamma + 64, beta + 64, 123008.0);

    // conv2 (winograd) -> pool+stats -> bn2
    winograd_kernel<62, false><<<dim3(16, 32, 2), 512>>>(pp1, w0, pU2, pa2, 1);
    poolstats_kernel<60, 29><<<2048, 256>>>(pa2, pp2);
    scalebias_kernel<<<1, 64>>>(2, gamma + 128, beta + 128, 26912.0);

    // conv3 (winograd) -> pool+stats -> bn3
    winograd_kernel<29, false><<<dim3(4, 32, 2), 512>>>(pp2, w0, pU3, pa3, 2);
    poolstats_kernel<27, 13><<<2048, 256>>>(pa3, pp3);
    scalebias_kernel<<<1, 64>>>(3, gamma + 192, beta + 192, 5408.0);

    fc_kernel<<<192, 256>>>(Wreg, breg);
    sn_kernel<<<1, 32>>>(u0, v0);
    sample_kernel<<<(32 * 16384 + 255) / 256, 256>>>(x, out);
}

// round 6
// speedup vs baseline: 1.3156x; 1.3156x over previous
#include <cuda_runtime.h>
#include <math.h>

#define BATCH 32

// scratch (device globals: sanctioned workaround for no-alloc rule)
__device__ float g_a1[32 * 64 * 126 * 126];
__device__ float g_p1[32 * 64 * 62 * 62];
__device__ float g_a2[32 * 64 * 60 * 60];
__device__ float g_p2[32 * 64 * 29 * 29];
__device__ float g_a3[32 * 64 * 27 * 27];
__device__ float g_p3[32 * 64 * 13 * 13];
__device__ double g_dsum[64];
__device__ double g_dsq[64];
__device__ double g_xs[9];
__device__ float g_scale[4][64];
__device__ float g_bias[4][64];
__device__ float g_traw[32 * 6];
__device__ float g_theta[32 * 6];

// ---------------------------------------------------------------------------
__global__ void zero_stats_kernel() {
    int t = threadIdx.x;
    if (t < 64) { g_dsum[t] = 0.0; g_dsq[t] = 0.0; }
    if (t < 9)  { g_xs[t] = 0.0; }
}

// second moments of x in fp32, double only at reduction tail
__global__ void statsx_kernel(const float* __restrict__ x) {
    __shared__ float red[256];
    float a[9];
#pragma unroll
    for (int i = 0; i < 9; i++) a[i] = 0.f;
    for (int idx = blockIdx.x * 256 + threadIdx.x; idx < BATCH * 16384;
         idx += gridDim.x * 256) {
        int b = idx >> 14, p = idx & 16383;
        float x0 = x[(b * 3 + 0) * 16384 + p];
        float x1 = x[(b * 3 + 1) * 16384 + p];
        float x2 = x[(b * 3 + 2) * 16384 + p];
        a[0] = fmaf(x0, x0, a[0]); a[1] = fmaf(x0, x1, a[1]);
        a[2] = fmaf(x0, x2, a[2]); a[3] = fmaf(x1, x1, a[3]);
        a[4] = fmaf(x1, x2, a[4]); a[5] = fmaf(x2, x2, a[5]);
        a[6] += x0; a[7] += x1; a[8] += x2;
    }
#pragma unroll
    for (int q = 0; q < 9; q++) {
        red[threadIdx.x] = a[q];
        __syncthreads();
        for (int o = 128; o > 0; o >>= 1) {
            if (threadIdx.x < o) red[threadIdx.x] += red[threadIdx.x + o];
            __syncthreads();
        }
        if (threadIdx.x == 0) atomicAdd(&g_xs[q], (double)red[0]);
        __syncthreads();
    }
}

__global__ void scalebias0_kernel(const float* __restrict__ w0,
                                  const float* __restrict__ gamma,
                                  const float* __restrict__ beta) {
    int o = threadIdx.x;
    if (o >= 64) return;
    const double N = 524288.0;
    double C00 = g_xs[0] / N, C01 = g_xs[1] / N, C02 = g_xs[2] / N;
    double C11 = g_xs[3] / N, C12 = g_xs[4] / N, C22 = g_xs[5] / N;
    double m0 = g_xs[6] / N, m1 = g_xs[7] / N, m2 = g_xs[8] / N;
    double w0v = w0[o * 3 + 0], w1v = w0[o * 3 + 1], w2v = w0[o * 3 + 2];
    double m = w0v * m0 + w1v * m1 + w2v * m2;
    double e2 = w0v * w0v * C00 + w1v * w1v * C11 + w2v * w2v * C22 +
                2.0 * (w0v * w1v * C01 + w0v * w2v * C02 + w1v * w2v * C12);
    double var = e2 - m * m;
    double sc = (double)gamma[o] / sqrt(var + 1e-5);
    g_scale[0][o] = (float)sc;
    g_bias[0][o] = (float)((double)beta[o] - m * sc);
}

// consumes stats for layer l, then re-zeroes the accumulators for next layer
__global__ void scalebias_kernel(int l, const float* __restrict__ gamma,
                                 const float* __restrict__ beta, double N) {
    int c = threadIdx.x;
    if (c >= 64) return;
    double m = g_dsum[c] / N;
    double var = g_dsq[c] / N - m * m;
    double sc = (double)gamma[c] / sqrt(var + 1e-5);
    g_scale[l][c] = (float)sc;
    g_bias[l][c] = (float)((double)beta[c] - m * sc);
    g_dsum[c] = 0.0;
    g_dsq[c] = 0.0;
}

// ---------------------------------------------------------------------------
// conv inner: OCB out-channels x (2 rows x 4 cols) per thread, 9 taps
template <int OCB>
__device__ __forceinline__ void conv_tile_accum(const float* __restrict__ in_s,
                                                const float* __restrict__ ws,
                                                float acc[OCB][8], int cg,
                                                int ry, int cx) {
    float vin[4][6];
#pragma unroll
    for (int r = 0; r < 4; r++) {
        const float* ip = &in_s[(ry + r) * 20 + cx];
#pragma unroll
        for (int c = 0; c < 6; c++) vin[r][c] = ip[c];
    }
#pragma unroll
    for (int ch = 0; ch < OCB; ch++) {
        const float* wp = &ws[(cg * OCB + ch) * 12];
        float w[9];
#pragma unroll
        for (int t = 0; t < 9; t++) w[t] = wp[t];
#pragma unroll
        for (int r = 0; r < 2; r++) {
#pragma unroll
            for (int c = 0; c < 4; c++) {
                float s = acc[ch][r * 4 + c];
                s = fmaf(vin[r][c],     w[0], s);
                s = fmaf(vin[r][c + 1], w[1], s);
                s = fmaf(vin[r][c + 2], w[2], s);
                s = fmaf(vin[r + 1][c],     w[3], s);
                s = fmaf(vin[r + 1][c + 1], w[4], s);
                s = fmaf(vin[r + 1][c + 2], w[5], s);
                s = fmaf(vin[r + 2][c],     w[6], s);
                s = fmaf(vin[r + 2][c + 1], w[7], s);
                s = fmaf(vin[r + 2][c + 2], w[8], s);
                acc[ch][r * 4 + c] = s;
            }
        }
    }
}

// conv1: recompute conv0+bn0+relu per tile from x, then 3x3 conv (direct)
__global__ __launch_bounds__(256, 2) void conv1_kernel(
    const float* __restrict__ x, const float* __restrict__ w0,
    const float* __restrict__ w1) {
    __shared__ float xs[3][18 * 20];
    __shared__ float in_s[18 * 20];
    __shared__ float ws[64 * 12];
    const int b = blockIdx.y;
    const int tx = blockIdx.x & 7, ty = blockIdx.x >> 3;
    const int oy0 = ty * 16, ox0 = tx * 16;
    const int tid = threadIdx.x;
    const int cg = tid >> 5;
    const int sp = tid & 31;
    const int ry = (sp >> 2) * 2, cx = (sp & 3) * 4;

    float acc[8][8];
#pragma unroll
    for (int i = 0; i < 8; i++)
#pragma unroll
        for (int j = 0; j < 8; j++) acc[i][j] = 0.f;

    for (int idx = tid; idx < 3 * 324; idx += 256) {
        int c = idx / 324, p = idx - c * 324;
        int iy = p / 18, ix = p - iy * 18;
        int gy = oy0 + iy, gx = ox0 + ix;
        float v = 0.f;
        if (gy < 128 && gx < 128) v = x[((b * 3 + c) * 128 + gy) * 128 + gx];
        xs[c][iy * 20 + ix] = v;
    }

    for (int cin = 0; cin < 64; cin++) {
        __syncthreads();
        float a0 = w0[cin * 3 + 0], a1 = w0[cin * 3 + 1], a2 = w0[cin * 3 + 2];
        float scl = g_scale[0][cin], bia = g_bias[0][cin];
        for (int idx = tid; idx < 324; idx += 256) {
            int iy = idx / 18, ix = idx - iy * 18;
            int o = iy * 20 + ix;
            float v = xs[0][o] * a0 + xs[1][o] * a1 + xs[2][o] * a2;
            in_s[o] = fmaxf(fmaf(v, scl, bia), 0.f);
        }
        for (int idx = tid; idx < 576; idx += 256) {
            int o = idx / 9, t = idx - o * 9;
            ws[o * 12 + t] = w1[(o * 64 + cin) * 9 + t];
        }
        __syncthreads();
        conv_tile_accum<8>(in_s, ws, acc, cg, ry, cx);
    }

#pragma unroll
    for (int ch = 0; ch < 8; ch++) {
        const int och = cg * 8 + ch;
        float* db = g_a1 + ((size_t)(b * 64 + och)) * 126 * 126;
#pragma unroll
        for (int r = 0; r < 2; r++) {
            int oy = oy0 + ry + r;
            if (oy >= 126) continue;
#pragma unroll
            for (int c = 0; c < 4; c++) {
                int ox = ox0 + cx + c;
                if (ox < 126) db[oy * 126 + ox] = acc[ch][r * 4 + c];
            }
        }
    }
}

// generic 3x3 conv; OCB out-channels per thread, oc-split via blockIdx.z
template <int IH, int OCB>
__global__ __launch_bounds__(256, 2) void conv3x3_kernel(
    const float* __restrict__ src, const float* __restrict__ wconv,
    float* __restrict__ dst, int lidx) {
    constexpr int OH = IH - 2;
    constexpr int TX = (OH + 15) / 16;
    constexpr int NOC = 8 * OCB;
    __shared__ float in_s[18 * 20];
    __shared__ float ws[NOC * 12];
    const int b = blockIdx.y;
    const int oc0 = blockIdx.z * NOC;
    const int tx = blockIdx.x % TX, ty = blockIdx.x / TX;
    const int oy0 = ty * 16, ox0 = tx * 16;
    const int tid = threadIdx.x;
    const int cg = tid >> 5;
    const int sp = tid & 31;
    const int ry = (sp >> 2) * 2, cx = (sp & 3) * 4;

    float acc[OCB][8];
#pragma unroll
    for (int i = 0; i < OCB; i++)
#pragma unroll
        for (int j = 0; j < 8; j++) acc[i][j] = 0.f;

    for (int cin = 0; cin < 64; cin++) {
        __syncthreads();
        float scl = g_scale[lidx][cin], bia = g_bias[lidx][cin];
        const float* sb = src + ((size_t)(b * 64 + cin)) * IH * IH;
        for (int idx = tid; idx < 324; idx += 256) {
            int iy = idx / 18, ix = idx - iy * 18;
            int gy = oy0 + iy, gx = ox0 + ix;
            float v = 0.f;
            if (gy < IH && gx < IH) v = sb[gy * IH + gx];
            in_s[iy * 20 + ix] = fmaxf(fmaf(v, scl, bia), 0.f);
        }
        for (int idx = tid; idx < NOC * 9; idx += 256) {
            int o = idx / 9, t = idx - o * 9;
            ws[o * 12 + t] = wconv[((oc0 + o) * 64 + cin) * 9 + t];
        }
        __syncthreads();
        conv_tile_accum<OCB>(in_s, ws, acc, cg, ry, cx);
    }

#pragma unroll
    for (int ch = 0; ch < OCB; ch++) {
        const int och = oc0 + cg * OCB + ch;
        float* db = dst + ((size_t)(b * 64 + och)) * OH * OH;
#pragma unroll
        for (int r = 0; r < 2; r++) {
            int oy = oy0 + ry + r;
            if (oy >= OH) continue;
#pragma unroll
            for (int c = 0; c < 4; c++) {
                int ox = ox0 + cx + c;
                if (ox < OH) db[oy * OH + ox] = acc[ch][r * 4 + c];
            }
        }
    }
}

// ---------------------------------------------------------------------------
// fused maxpool(3,2) + per-channel stats: one block per (b,c) plane
template <int CH, int PH>
__global__ void poolstats_kernel(const float* __restrict__ src,
                                 float* __restrict__ dst) {
    __shared__ float r1[256], r2[256];
    int bc = blockIdx.x;
    int c = bc & 63;
    const float* sb = src + (size_t)bc * CH * CH;
    float* db = dst + (size_t)bc * PH * PH;
    float s = 0.f, q = 0.f;
    for (int i = threadIdx.x; i < PH * PH; i += 256) {
        int py = i / PH, px = i - py * PH;
        const float* w = sb + (2 * py) * CH + 2 * px;
        float m = w[0];
#pragma unroll
        for (int di = 0; di < 3; di++)
#pragma unroll
            for (int dj = 0; dj < 3; dj++) m = fmaxf(m, w[di * CH + dj]);
        db[i] = m;
        s += m;
        q = fmaf(m, m, q);
    }
    r1[threadIdx.x] = s; r2[threadIdx.x] = q;
    __syncthreads();
    for (int o = 128; o > 0; o >>= 1) {
        if (threadIdx.x < o) {
            r1[threadIdx.x] += r1[threadIdx.x + o];
            r2[threadIdx.x] += r2[threadIdx.x + o];
        }
        __syncthreads();
    }
    if (threadIdx.x == 0) {
        atomicAdd(&g_dsum[c], (double)r1[0]);
        atomicAdd(&g_dsq[c], (double)r2[0]);
    }
}

// ---------------------------------------------------------------------------
__global__ void fc_kernel(const float* __restrict__ Wreg,
                          const float* __restrict__ breg) {
    __shared__ float red[256];
    int j = blockIdx.x % 6, b = blockIdx.x / 6;
    const float* pb = g_p3 + (size_t)b * 10816;
    const float* wb = Wreg + (size_t)j * 10816;
    float s = 0.f;
    for (int k = threadIdx.x; k < 10816; k += 256) {
        int c = k / 169;
        float v = fmaxf(fmaf(pb[k], g_scale[3][c], g_bias[3][c]), 0.f);
        s += v * wb[k];
    }
    red[threadIdx.x] = s;
    __syncthreads();
    for (int o = 128; o > 0; o >>= 1) {
        if (threadIdx.x < o) red[threadIdx.x] += red[threadIdx.x + o];
        __syncthreads();
    }
    if (threadIdx.x == 0) g_traw[b * 6 + j] = red[0] + breg[j];
}

__global__ void sn_kernel(const float* __restrict__ u0,
                          const float* __restrict__ v0) {
    if (threadIdx.x != 0 || blockIdx.x != 0) return;
    float u[2] = {u0[0], u0[1]};
    float v[3] = {v0[0], v0[1], v0[2]};
    for (int b = 0; b < 32; b++) {
        float W[6];
#pragma unroll
        for (int i = 0; i < 6; i++) W[i] = g_traw[b * 6 + i];
#pragma unroll
        for (int it = 0; it < 4; it++) {
            float nv[3];
#pragma unroll
            for (int j = 0; j < 3; j++) nv[j] = W[j] * u[0] + W[3 + j] * u[1];
            float n = sqrtf(nv[0] * nv[0] + nv[1] * nv[1] + nv[2] * nv[2]);
            n = fmaxf(n, 1e-12f);
#pragma unroll
            for (int j = 0; j < 3; j++) v[j] = nv[j] / n;
            float nu0 = W[0] * v[0] + W[1] * v[1] + W[2] * v[2];
            float nu1 = W[3] * v[0] + W[4] * v[1] + W[5] * v[2];
            n = sqrtf(nu0 * nu0 + nu1 * nu1);
            n = fmaxf(n, 1e-12f);
            u[0] = nu0 / n; u[1] = nu1 / n;
        }
        float Wv0 = W[0] * v[0] + W[1] * v[1] + W[2] * v[2];
        float Wv1 = W[3] * v[0] + W[4] * v[1] + W[5] * v[2];
        float sigma = u[0] * Wv0 + u[1] * Wv1;
#pragma unroll
        for (int i = 0; i < 6; i++) g_theta[b * 6 + i] = W[i] / sigma;
    }
}

__global__ void sample_kernel(const float* __restrict__ x,
                              float* __restrict__ out) {
    int idx = blockIdx.x * 256 + threadIdx.x;
    if (idx >= BATCH * 16384) return;
    int b = idx >> 14, p = idx & 16383;
    int h = p >> 7, w = p & 127;
    const float* th = &g_theta[b * 6];
    float xsc = (2.f * w + 1.f) / 128.f - 1.f;
    float ysc = (2.f * h + 1.f) / 128.f - 1.f;
    float gx = th[0] * xsc + th[1] * ysc + th[2];
    float gy = th[3] * xsc + th[4] * ysc + th[5];
    float ix = ((gx + 1.f) * 128.f - 1.f) * 0.5f;
    float iy = ((gy + 1.f) * 128.f - 1.f) * 0.5f;
    float r = fmodf(fabsf(ix + 0.5f), 256.f);
    ix = (r > 128.f ? 256.f - r : r) - 0.5f;
    ix = fminf(fmaxf(ix, 0.f), 127.f);
    r = fmodf(fabsf(iy + 0.5f), 256.f);
    iy = (r > 128.f ? 256.f - r : r) - 0.5f;
    iy = fminf(fmaxf(iy, 0.f), 127.f);
    float fx0 = floorf(ix), fy0 = floorf(iy);
    float wx = ix - fx0, wy = iy - fy0;
    int x0 = min(max((int)fx0, 0), 127), y0 = min(max((int)fy0, 0), 127);
    int x1 = min(x0 + 1, 127), y1 = min(y0 + 1, 127);
    float w00 = (1.f - wx) * (1.f - wy), w10 = wx * (1.f - wy);
    float w01 = (1.f - wx) * wy, w11 = wx * wy;
#pragma unroll
    for (int c = 0; c < 3; c++) {
        const float* xb = x + (size_t)(b * 3 + c) * 16384;
        float v = xb[y0 * 128 + x0] * w00 + xb[y0 * 128 + x1] * w10 +
                  xb[y1 * 128 + x0] * w01 + xb[y1 * 128 + x1] * w11;
        out[(size_t)(b * 3 + c) * 16384 + p] = v;
    }
}

// ---------------------------------------------------------------------------
extern "C" void kernel_launch(void* const* d_in, const int* in_sizes, int n_in,
                              void* d_out, int out_size) {
    const float* x     = (const float*)d_in[0];
    const float* w0    = (const float*)d_in[1];
    const float* w1    = (const float*)d_in[2];
    const float* w2    = (const float*)d_in[3];
    const float* w3    = (const float*)d_in[4];
    const float* gamma = (const float*)d_in[5];
    const float* beta  = (const float*)d_in[6];
    const float* Wreg  = (const float*)d_in[7];
    const float* breg  = (const float*)d_in[8];
    const float* u0    = (const float*)d_in[9];
    const float* v0    = (const float*)d_in[10];
    float* out = (float*)d_out;
    (void)n_in; (void)in_sizes; (void)out_size;

    float *pa1, *pp1, *pa2, *pp2, *pa3, *pp3;
    cudaGetSymbolAddress((void**)&pa1, g_a1);
    cudaGetSymbolAddress((void**)&pp1, g_p1);
    cudaGetSymbolAddress((void**)&pa2, g_a2);
    cudaGetSymbolAddress((void**)&pp2, g_p2);
    cudaGetSymbolAddress((void**)&pa3, g_a3);
    cudaGetSymbolAddress((void**)&pp3, g_p3);

    zero_stats_kernel<<<1, 256>>>();
    statsx_kernel<<<512, 256>>>(x);
    scalebias0_kernel<<<1, 64>>>(w0, gamma, beta);

    // conv1 (direct, fused conv0+bn0+relu) -> fused pool+stats -> bn1
    conv1_kernel<<<dim3(64, 32), 256>>>(x, w0, w1);
    poolstats_kernel<126, 62><<<2048, 256>>>(pa1, pp1);
    scalebias_kernel<<<1, 64>>>(1, gamma + 64, beta + 64, 123008.0);

    // conv2 (direct) -> fused pool+stats -> bn2
    conv3x3_kernel<62, 8><<<dim3(16, 32, 1), 256>>>(pp1, w2, pa2, 1);
    poolstats_kernel<60, 29><<<2048, 256>>>(pa2, pp2);
    scalebias_kernel<<<1, 64>>>(2, gamma + 128, beta + 128, 26912.0);

    // conv3 (direct, oc-split x2) -> fused pool+stats -> bn3
    conv3x3_kernel<29, 4><<<dim3(4, 32, 2), 256>>>(pp2, w3, pa3, 2);
    poolstats_kernel<27, 13><<<2048, 256>>>(pa3, pp3);
    scalebias_kernel<<<1, 64>>>(3, gamma + 192, beta + 192, 5408.0);

    fc_kernel<<<192, 256>>>(Wreg, breg);
    sn_kernel<<<1, 32>>>(u0, v0);
    sample_kernel<<<(32 * 16384 + 255) / 256, 256>>>(x, out);
}

// round 7
// speedup vs baseline: 1.4448x; 1.0982x over previous
#include <cuda_runtime.h>
#include <math.h>

#define BATCH 32

// scratch (device globals: sanctioned workaround for no-alloc rule)
__device__ float g_a1[32 * 64 * 126 * 126];
__device__ float g_p1[32 * 64 * 62 * 62];
__device__ float g_a2[32 * 64 * 60 * 60];
__device__ float g_p2[32 * 64 * 29 * 29];
__device__ float g_a3[32 * 64 * 27 * 27];
__device__ float g_p3[32 * 64 * 13 * 13];
__device__ double g_dsum[64];   // zero-init at load; re-zeroed after each use
__device__ double g_dsq[64];
__device__ double g_xs[9];
__device__ float g_scale[4][64];
__device__ float g_bias[4][64];
__device__ float g_traw[32 * 6];
__device__ float g_theta[32 * 6];

// ---------------------------------------------------------------------------
// second moments of x in fp32, double only at reduction tail
__global__ void statsx_kernel(const float* __restrict__ x) {
    __shared__ float red[256];
    float a[9];
#pragma unroll
    for (int i = 0; i < 9; i++) a[i] = 0.f;
    for (int idx = blockIdx.x * 256 + threadIdx.x; idx < BATCH * 16384;
         idx += gridDim.x * 256) {
        int b = idx >> 14, p = idx & 16383;
        float x0 = x[(b * 3 + 0) * 16384 + p];
        float x1 = x[(b * 3 + 1) * 16384 + p];
        float x2 = x[(b * 3 + 2) * 16384 + p];
        a[0] = fmaf(x0, x0, a[0]); a[1] = fmaf(x0, x1, a[1]);
        a[2] = fmaf(x0, x2, a[2]); a[3] = fmaf(x1, x1, a[3]);
        a[4] = fmaf(x1, x2, a[4]); a[5] = fmaf(x2, x2, a[5]);
        a[6] += x0; a[7] += x1; a[8] += x2;
    }
#pragma unroll
    for (int q = 0; q < 9; q++) {
        red[threadIdx.x] = a[q];
        __syncthreads();
        for (int o = 128; o > 0; o >>= 1) {
            if (threadIdx.x < o) red[threadIdx.x] += red[threadIdx.x + o];
            __syncthreads();
        }
        if (threadIdx.x == 0) atomicAdd(&g_xs[q], (double)red[0]);
        __syncthreads();
    }
}

// analytic BN0 from x moments; zeroes g_xs after consuming (replay-safe)
__global__ void scalebias0_kernel(const float* __restrict__ w0,
                                  const float* __restrict__ gamma,
                                  const float* __restrict__ beta) {
    int o = threadIdx.x;
    if (o >= 64) return;
    const double N = 524288.0;
    double C00 = g_xs[0] / N, C01 = g_xs[1] / N, C02 = g_xs[2] / N;
    double C11 = g_xs[3] / N, C12 = g_xs[4] / N, C22 = g_xs[5] / N;
    double m0 = g_xs[6] / N, m1 = g_xs[7] / N, m2 = g_xs[8] / N;
    __syncthreads();
    if (o < 9) g_xs[o] = 0.0;
    double w0v = w0[o * 3 + 0], w1v = w0[o * 3 + 1], w2v = w0[o * 3 + 2];
    double m = w0v * m0 + w1v * m1 + w2v * m2;
    double e2 = w0v * w0v * C00 + w1v * w1v * C11 + w2v * w2v * C22 +
                2.0 * (w0v * w1v * C01 + w0v * w2v * C02 + w1v * w2v * C12);
    double var = e2 - m * m;
    double sc = (double)gamma[o] / sqrt(var + 1e-5);
    g_scale[0][o] = (float)sc;
    g_bias[0][o] = (float)((double)beta[o] - m * sc);
}

// consumes stats for layer l, then re-zeroes accumulators (replay-safe)
__global__ void scalebias_kernel(int l, const float* __restrict__ gamma,
                                 const float* __restrict__ beta, double N) {
    int c = threadIdx.x;
    if (c >= 64) return;
    double m = g_dsum[c] / N;
    double var = g_dsq[c] / N - m * m;
    double sc = (double)gamma[c] / sqrt(var + 1e-5);
    g_scale[l][c] = (float)sc;
    g_bias[l][c] = (float)((double)beta[c] - m * sc);
    g_dsum[c] = 0.0;
    g_dsq[c] = 0.0;
}

// ---------------------------------------------------------------------------
// conv inner: OCB out-channels x (2 rows x 4 cols) per thread, 9 taps
template <int OCB>
__device__ __forceinline__ void conv_tile_accum(const float* __restrict__ in_s,
                                                const float* __restrict__ ws,
                                                float acc[OCB][8], int cg,
                                                int ry, int cx) {
    float vin[4][6];
#pragma unroll
    for (int r = 0; r < 4; r++) {
        const float* ip = &in_s[(ry + r) * 20 + cx];
#pragma unroll
        for (int c = 0; c < 6; c++) vin[r][c] = ip[c];
    }
#pragma unroll
    for (int ch = 0; ch < OCB; ch++) {
        const float* wp = &ws[(cg * OCB + ch) * 12];
        float w[9];
#pragma unroll
        for (int t = 0; t < 9; t++) w[t] = wp[t];
#pragma unroll
        for (int r = 0; r < 2; r++) {
#pragma unroll
            for (int c = 0; c < 4; c++) {
                float s = acc[ch][r * 4 + c];
                s = fmaf(vin[r][c],     w[0], s);
                s = fmaf(vin[r][c + 1], w[1], s);
                s = fmaf(vin[r][c + 2], w[2], s);
                s = fmaf(vin[r + 1][c],     w[3], s);
                s = fmaf(vin[r + 1][c + 1], w[4], s);
                s = fmaf(vin[r + 1][c + 2], w[5], s);
                s = fmaf(vin[r + 2][c],     w[6], s);
                s = fmaf(vin[r + 2][c + 1], w[7], s);
                s = fmaf(vin[r + 2][c + 2], w[8], s);
                acc[ch][r * 4 + c] = s;
            }
        }
    }
}

// conv1: recompute conv0+bn0+relu per tile from x, then 3x3 conv (direct).
// Double-buffered staging: one barrier per cin.
__global__ __launch_bounds__(256, 2) void conv1_kernel(
    const float* __restrict__ x, const float* __restrict__ w0,
    const float* __restrict__ w1) {
    __shared__ float xs[3][360];
    __shared__ float in_s[2][360];
    __shared__ float ws[2][64 * 12];
    const int b = blockIdx.y;
    const int tx = blockIdx.x & 7, ty = blockIdx.x >> 3;
    const int oy0 = ty * 16, ox0 = tx * 16;
    const int tid = threadIdx.x;
    const int cg = tid >> 5;
    const int sp = tid & 31;
    const int ry = (sp >> 2) * 2, cx = (sp & 3) * 4;

    float acc[8][8];
#pragma unroll
    for (int i = 0; i < 8; i++)
#pragma unroll
        for (int j = 0; j < 8; j++) acc[i][j] = 0.f;

    for (int idx = tid; idx < 3 * 324; idx += 256) {
        int c = idx / 324, p = idx - c * 324;
        int iy = p / 18, ix = p - iy * 18;
        int gy = oy0 + iy, gx = ox0 + ix;
        float v = 0.f;
        if (gy < 128 && gx < 128) v = x[((b * 3 + c) * 128 + gy) * 128 + gx];
        xs[c][iy * 20 + ix] = v;
    }
    __syncthreads();

    auto stage = [&](int cin, int bf) {
        float a0 = w0[cin * 3 + 0], a1 = w0[cin * 3 + 1], a2 = w0[cin * 3 + 2];
        float scl = g_scale[0][cin], bia = g_bias[0][cin];
        for (int idx = tid; idx < 324; idx += 256) {
            int iy = idx / 18, ix = idx - iy * 18;
            int o = iy * 20 + ix;
            float v = xs[0][o] * a0 + xs[1][o] * a1 + xs[2][o] * a2;
            in_s[bf][o] = fmaxf(fmaf(v, scl, bia), 0.f);
        }
        for (int idx = tid; idx < 576; idx += 256) {
            int o = idx / 9, t = idx - o * 9;
            ws[bf][o * 12 + t] = w1[(o * 64 + cin) * 9 + t];
        }
    };

    stage(0, 0);
    __syncthreads();
    for (int cin = 0; cin < 64; cin++) {
        int cur = cin & 1;
        if (cin + 1 < 64) stage(cin + 1, cur ^ 1);
        conv_tile_accum<8>(in_s[cur], ws[cur], acc, cg, ry, cx);
        __syncthreads();
    }

#pragma unroll
    for (int ch = 0; ch < 8; ch++) {
        const int och = cg * 8 + ch;
        float* db = g_a1 + ((size_t)(b * 64 + och)) * 126 * 126;
#pragma unroll
        for (int r = 0; r < 2; r++) {
            int oy = oy0 + ry + r;
            if (oy >= 126) continue;
#pragma unroll
            for (int c = 0; c < 4; c++) {
                int ox = ox0 + cx + c;
                if (ox < 126) db[oy * 126 + ox] = acc[ch][r * 4 + c];
            }
        }
    }
}

// generic 3x3 conv; OCB out-channels per thread, oc-split via blockIdx.z.
// Double-buffered staging: one barrier per cin.
template <int IH, int OCB>
__global__ __launch_bounds__(256, 2) void conv3x3_kernel(
    const float* __restrict__ src, const float* __restrict__ wconv,
    float* __restrict__ dst, int lidx) {
    constexpr int OH = IH - 2;
    constexpr int TX = (OH + 15) / 16;
    constexpr int NOC = 8 * OCB;
    __shared__ float in_s[2][360];
    __shared__ float ws[2][NOC * 12];
    const int b = blockIdx.y;
    const int oc0 = blockIdx.z * NOC;
    const int tx = blockIdx.x % TX, ty = blockIdx.x / TX;
    const int oy0 = ty * 16, ox0 = tx * 16;
    const int tid = threadIdx.x;
    const int cg = tid >> 5;
    const int sp = tid & 31;
    const int ry = (sp >> 2) * 2, cx = (sp & 3) * 4;

    float acc[OCB][8];
#pragma unroll
    for (int i = 0; i < OCB; i++)
#pragma unroll
        for (int j = 0; j < 8; j++) acc[i][j] = 0.f;

    auto stage = [&](int cin, int bf) {
        float scl = g_scale[lidx][cin], bia = g_bias[lidx][cin];
        const float* sb = src + ((size_t)(b * 64 + cin)) * IH * IH;
        for (int idx = tid; idx < 324; idx += 256) {
            int iy = idx / 18, ix = idx - iy * 18;
            int gy = oy0 + iy, gx = ox0 + ix;
            float v = 0.f;
            if (gy < IH && gx < IH) v = sb[gy * IH + gx];
            in_s[bf][iy * 20 + ix] = fmaxf(fmaf(v, scl, bia), 0.f);
        }
        for (int idx = tid; idx < NOC * 9; idx += 256) {
            int o = idx / 9, t = idx - o * 9;
            ws[bf][o * 12 + t] = wconv[((oc0 + o) * 64 + cin) * 9 + t];
        }
    };

    stage(0, 0);
    __syncthreads();
    for (int cin = 0; cin < 64; cin++) {
        int cur = cin & 1;
        if (cin + 1 < 64) stage(cin + 1, cur ^ 1);
        conv_tile_accum<OCB>(in_s[cur], ws[cur], acc, cg, ry, cx);
        __syncthreads();
    }

#pragma unroll
    for (int ch = 0; ch < OCB; ch++) {
        const int och = oc0 + cg * OCB + ch;
        float* db = dst + ((size_t)(b * 64 + och)) * OH * OH;
#pragma unroll
        for (int r = 0; r < 2; r++) {
            int oy = oy0 + ry + r;
            if (oy >= OH) continue;
#pragma unroll
            for (int c = 0; c < 4; c++) {
                int ox = ox0 + cx + c;
                if (ox < OH) db[oy * OH + ox] = acc[ch][r * 4 + c];
            }
        }
    }
}

// ---------------------------------------------------------------------------
// fused maxpool(3,2) + per-channel stats: one block per (b,c) plane
template <int CH, int PH>
__global__ void poolstats_kernel(const float* __restrict__ src,
                                 float* __restrict__ dst) {
    __shared__ float r1[256], r2[256];
    int bc = blockIdx.x;
    int c = bc & 63;
    const float* sb = src + (size_t)bc * CH * CH;
    float* db = dst + (size_t)bc * PH * PH;
    float s = 0.f, q = 0.f;
    for (int i = threadIdx.x; i < PH * PH; i += 256) {
        int py = i / PH, px = i - py * PH;
        const float* w = sb + (2 * py) * CH + 2 * px;
        float m = w[0];
#pragma unroll
        for (int di = 0; di < 3; di++)
#pragma unroll
            for (int dj = 0; dj < 3; dj++) m = fmaxf(m, w[di * CH + dj]);
        db[i] = m;
        s += m;
        q = fmaf(m, m, q);
    }
    r1[threadIdx.x] = s; r2[threadIdx.x] = q;
    __syncthreads();
    for (int o = 128; o > 0; o >>= 1) {
        if (threadIdx.x < o) {
            r1[threadIdx.x] += r1[threadIdx.x + o];
            r2[threadIdx.x] += r2[threadIdx.x + o];
        }
        __syncthreads();
    }
    if (threadIdx.x == 0) {
        atomicAdd(&g_dsum[c], (double)r1[0]);
        atomicAdd(&g_dsq[c], (double)r2[0]);
    }
}

// ---------------------------------------------------------------------------
__global__ void fc_kernel(const float* __restrict__ Wreg,
                          const float* __restrict__ breg) {
    __shared__ float red[256];
    int j = blockIdx.x % 6, b = blockIdx.x / 6;
    const float* pb = g_p3 + (size_t)b * 10816;
    const float* wb = Wreg + (size_t)j * 10816;
    float s = 0.f;
    for (int k = threadIdx.x; k < 10816; k += 256) {
        int c = k / 169;
        float v = fmaxf(fmaf(pb[k], g_scale[3][c], g_bias[3][c]), 0.f);
        s += v * wb[k];
    }
    red[threadIdx.x] = s;
    __syncthreads();
    for (int o = 128; o > 0; o >>= 1) {
        if (threadIdx.x < o) red[threadIdx.x] += red[threadIdx.x + o];
        __syncthreads();
    }
    if (threadIdx.x == 0) g_traw[b * 6 + j] = red[0] + breg[j];
}

__global__ void sn_kernel(const float* __restrict__ u0,
                          const float* __restrict__ v0) {
    if (threadIdx.x != 0 || blockIdx.x != 0) return;
    float u[2] = {u0[0], u0[1]};
    float v[3] = {v0[0], v0[1], v0[2]};
    for (int b = 0; b < 32; b++) {
        float W[6];
#pragma unroll
        for (int i = 0; i < 6; i++) W[i] = g_traw[b * 6 + i];
#pragma unroll
        for (int it = 0; it < 4; it++) {
            float nv[3];
#pragma unroll
            for (int j = 0; j < 3; j++) nv[j] = W[j] * u[0] + W[3 + j] * u[1];
            float n = sqrtf(nv[0] * nv[0] + nv[1] * nv[1] + nv[2] * nv[2]);
            n = fmaxf(n, 1e-12f);
#pragma unroll
            for (int j = 0; j < 3; j++) v[j] = nv[j] / n;
            float nu0 = W[0] * v[0] + W[1] * v[1] + W[2] * v[2];
            float nu1 = W[3] * v[0] + W[4] * v[1] + W[5] * v[2];
            n = sqrtf(nu0 * nu0 + nu1 * nu1);
            n = fmaxf(n, 1e-12f);
            u[0] = nu0 / n; u[1] = nu1 / n;
        }
        float Wv0 = W[0] * v[0] + W[1] * v[1] + W[2] * v[2];
        float Wv1 = W[3] * v[0] + W[4] * v[1] + W[5] * v[2];
        float sigma = u[0] * Wv0 + u[1] * Wv1;
#pragma unroll
        for (int i = 0; i < 6; i++) g_theta[b * 6 + i] = W[i] / sigma;
    }
}

__global__ void sample_kernel(const float* __restrict__ x,
                              float* __restrict__ out) {
    int idx = blockIdx.x * 256 + threadIdx.x;
    if (idx >= BATCH * 16384) return;
    int b = idx >> 14, p = idx & 16383;
    int h = p >> 7, w = p & 127;
    const float* th = &g_theta[b * 6];
    float xsc = (2.f * w + 1.f) / 128.f - 1.f;
    float ysc = (2.f * h + 1.f) / 128.f - 1.f;
    float gx = th[0] * xsc + th[1] * ysc + th[2];
    float gy = th[3] * xsc + th[4] * ysc + th[5];
    float ix = ((gx + 1.f) * 128.f - 1.f) * 0.5f;
    float iy = ((gy + 1.f) * 128.f - 1.f) * 0.5f;
    float r = fmodf(fabsf(ix + 0.5f), 256.f);
    ix = (r > 128.f ? 256.f - r : r) - 0.5f;
    ix = fminf(fmaxf(ix, 0.f), 127.f);
    r = fmodf(fabsf(iy + 0.5f), 256.f);
    iy = (r > 128.f ? 256.f - r : r) - 0.5f;
    iy = fminf(fmaxf(iy, 0.f), 127.f);
    float fx0 = floorf(ix), fy0 = floorf(iy);
    float wx = ix - fx0, wy = iy - fy0;
    int x0 = min(max((int)fx0, 0), 127), y0 = min(max((int)fy0, 0), 127);
    int x1 = min(x0 + 1, 127), y1 = min(y0 + 1, 127);
    float w00 = (1.f - wx) * (1.f - wy), w10 = wx * (1.f - wy);
    float w01 = (1.f - wx) * wy, w11 = wx * wy;
#pragma unroll
    for (int c = 0; c < 3; c++) {
        const float* xb = x + (size_t)(b * 3 + c) * 16384;
        float v = xb[y0 * 128 + x0] * w00 + xb[y0 * 128 + x1] * w10 +
                  xb[y1 * 128 + x0] * w01 + xb[y1 * 128 + x1] * w11;
        out[(size_t)(b * 3 + c) * 16384 + p] = v;
    }
}

// ---------------------------------------------------------------------------
extern "C" void kernel_launch(void* const* d_in, const int* in_sizes, int n_in,
                              void* d_out, int out_size) {
    const float* x     = (const float*)d_in[0];
    const float* w0    = (const float*)d_in[1];
    const float* w1    = (const float*)d_in[2];
    const float* w2    = (const float*)d_in[3];
    const float* w3    = (const float*)d_in[4];
    const float* gamma = (const float*)d_in[5];
    const float* beta  = (const float*)d_in[6];
    const float* Wreg  = (const float*)d_in[7];
    const float* breg  = (const float*)d_in[8];
    const float* u0    = (const float*)d_in[9];
    const float* v0    = (const float*)d_in[10];
    float* out = (float*)d_out;
    (void)n_in; (void)in_sizes; (void)out_size;

    float *pa1, *pp1, *pa2, *pp2, *pa3, *pp3;
    cudaGetSymbolAddress((void**)&pa1, g_a1);
    cudaGetSymbolAddress((void**)&pp1, g_p1);
    cudaGetSymbolAddress((void**)&pa2, g_a2);
    cudaGetSymbolAddress((void**)&pp2, g_p2);
    cudaGetSymbolAddress((void**)&pa3, g_a3);
    cudaGetSymbolAddress((void**)&pp3, g_p3);

    statsx_kernel<<<512, 256>>>(x);
    scalebias0_kernel<<<1, 64>>>(w0, gamma, beta);

    // conv1 (direct, fused conv0+bn0+relu) -> fused pool+stats -> bn1
    conv1_kernel<<<dim3(64, 32), 256>>>(x, w0, w1);
    poolstats_kernel<126, 62><<<2048, 256>>>(pa1, pp1);
    scalebias_kernel<<<1, 64>>>(1, gamma + 64, beta + 64, 123008.0);

    // conv2 (direct) -> fused pool+stats -> bn2
    conv3x3_kernel<62, 8><<<dim3(16, 32, 1), 256>>>(pp1, w2, pa2, 1);
    poolstats_kernel<60, 29><<<2048, 256>>>(pa2, pp2);
    scalebias_kernel<<<1, 64>>>(2, gamma + 128, beta + 128, 26912.0);

    // conv3 (direct, oc-split x2) -> fused pool+stats -> bn3
    conv3x3_kernel<29, 4><<<dim3(4, 32, 2), 256>>>(pp2, w3, pa3, 2);
    poolstats_kernel<27, 13><<<2048, 256>>>(pa3, pp3);
    scalebias_kernel<<<1, 64>>>(3, gamma + 192, beta + 192, 5408.0);

    fc_kernel<<<192, 256>>>(Wreg, breg);
    sn_kernel<<<1, 32>>>(u0, v0);
    sample_kernel<<<(32 * 16384 + 255) / 256, 256>>>(x, out);
}

// round 8
// speedup vs baseline: 1.4638x; 1.0131x over previous
#include <cuda_runtime.h>
#include <math.h>

#define BATCH 32

// scratch (device globals: sanctioned workaround for no-alloc rule)
__device__ float g_a1[32 * 64 * 126 * 126];
__device__ float g_p1[32 * 64 * 62 * 62];
__device__ float g_a2[32 * 64 * 60 * 60];
__device__ float g_p2[32 * 64 * 29 * 29];
__device__ float g_a3[32 * 64 * 27 * 27];
__device__ float g_p3[32 * 64 * 13 * 13];
__device__ double g_dsum[64];   // zero-init; re-zeroed after each consume
__device__ double g_dsq[64];
__device__ double g_xs[9];
__device__ float g_scale[4][64];
__device__ float g_bias[4][64];
__device__ float g_traw[32 * 6];
__device__ float g_theta[32 * 6];
__device__ int g_cnt0, g_cnt1, g_cnt2;   // last-block counters (self-reset)

// ---------------------------------------------------------------------------
// statsx: second moments of x; LAST BLOCK computes analytic BN0 scale/bias.
__global__ void statsx_kernel(const float* __restrict__ x,
                              const float* __restrict__ w0,
                              const float* __restrict__ gamma,
                              const float* __restrict__ beta) {
    __shared__ float red[256];
    __shared__ bool is_last;
    float a[9];
#pragma unroll
    for (int i = 0; i < 9; i++) a[i] = 0.f;
    for (int idx = blockIdx.x * 256 + threadIdx.x; idx < BATCH * 16384;
         idx += gridDim.x * 256) {
        int b = idx >> 14, p = idx & 16383;
        float x0 = x[(b * 3 + 0) * 16384 + p];
        float x1 = x[(b * 3 + 1) * 16384 + p];
        float x2 = x[(b * 3 + 2) * 16384 + p];
        a[0] = fmaf(x0, x0, a[0]); a[1] = fmaf(x0, x1, a[1]);
        a[2] = fmaf(x0, x2, a[2]); a[3] = fmaf(x1, x1, a[3]);
        a[4] = fmaf(x1, x2, a[4]); a[5] = fmaf(x2, x2, a[5]);
        a[6] += x0; a[7] += x1; a[8] += x2;
    }
#pragma unroll
    for (int q = 0; q < 9; q++) {
        red[threadIdx.x] = a[q];
        __syncthreads();
        for (int o = 128; o > 0; o >>= 1) {
            if (threadIdx.x < o) red[threadIdx.x] += red[threadIdx.x + o];
            __syncthreads();
        }
        if (threadIdx.x == 0) atomicAdd(&g_xs[q], (double)red[0]);
        __syncthreads();
    }
    // last-block: analytic BN0
    __threadfence();
    if (threadIdx.x == 0)
        is_last = (atomicAdd(&g_cnt0, 1) == (int)gridDim.x - 1);
    __syncthreads();
    if (!is_last) return;
    __threadfence();
    int o = threadIdx.x;
    if (o < 64) {
        const double N = 524288.0;
        double C00 = g_xs[0] / N, C01 = g_xs[1] / N, C02 = g_xs[2] / N;
        double C11 = g_xs[3] / N, C12 = g_xs[4] / N, C22 = g_xs[5] / N;
        double m0 = g_xs[6] / N, m1 = g_xs[7] / N, m2 = g_xs[8] / N;
        double w0v = w0[o * 3 + 0], w1v = w0[o * 3 + 1], w2v = w0[o * 3 + 2];
        double m = w0v * m0 + w1v * m1 + w2v * m2;
        double e2 = w0v * w0v * C00 + w1v * w1v * C11 + w2v * w2v * C22 +
                    2.0 * (w0v * w1v * C01 + w0v * w2v * C02 + w1v * w2v * C12);
        double var = e2 - m * m;
        double sc = (double)gamma[o] / sqrt(var + 1e-5);
        g_scale[0][o] = (float)sc;
        g_bias[0][o] = (float)((double)beta[o] - m * sc);
    }
    __syncthreads();
    if (threadIdx.x < 9) g_xs[threadIdx.x] = 0.0;
    if (threadIdx.x == 0) g_cnt0 = 0;
}

// ---------------------------------------------------------------------------
// conv inner: OCB out-channels x (2 rows x 4 cols) per thread, 9 taps
template <int OCB>
__device__ __forceinline__ void conv_tile_accum(const float* __restrict__ in_s,
                                                const float* __restrict__ ws,
                                                float acc[OCB][8], int cg,
                                                int ry, int cx) {
    float vin[4][6];
#pragma unroll
    for (int r = 0; r < 4; r++) {
        const float* ip = &in_s[(ry + r) * 20 + cx];
#pragma unroll
        for (int c = 0; c < 6; c++) vin[r][c] = ip[c];
    }
#pragma unroll
    for (int ch = 0; ch < OCB; ch++) {
        const float* wp = &ws[(cg * OCB + ch) * 12];
        float w[9];
#pragma unroll
        for (int t = 0; t < 9; t++) w[t] = wp[t];
#pragma unroll
        for (int r = 0; r < 2; r++) {
#pragma unroll
            for (int c = 0; c < 4; c++) {
                float s = acc[ch][r * 4 + c];
                s = fmaf(vin[r][c],     w[0], s);
                s = fmaf(vin[r][c + 1], w[1], s);
                s = fmaf(vin[r][c + 2], w[2], s);
                s = fmaf(vin[r + 1][c],     w[3], s);
                s = fmaf(vin[r + 1][c + 1], w[4], s);
                s = fmaf(vin[r + 1][c + 2], w[5], s);
                s = fmaf(vin[r + 2][c],     w[6], s);
                s = fmaf(vin[r + 2][c + 1], w[7], s);
                s = fmaf(vin[r + 2][c + 2], w[8], s);
                acc[ch][r * 4 + c] = s;
            }
        }
    }
}

// conv1: recompute conv0+bn0+relu per tile from x, then 3x3 conv (direct).
// Quad-buffered staging: one barrier per TWO cins.
__global__ __launch_bounds__(256, 2) void conv1_kernel(
    const float* __restrict__ x, const float* __restrict__ w0,
    const float* __restrict__ w1) {
    __shared__ float xs[3][360];
    __shared__ float in_s[4][360];
    __shared__ float ws[4][64 * 12];
    const int b = blockIdx.y;
    const int tx = blockIdx.x & 7, ty = blockIdx.x >> 3;
    const int oy0 = ty * 16, ox0 = tx * 16;
    const int tid = threadIdx.x;
    const int cg = tid >> 5;
    const int sp = tid & 31;
    const int ry = (sp >> 2) * 2, cx = (sp & 3) * 4;

    float acc[8][8];
#pragma unroll
    for (int i = 0; i < 8; i++)
#pragma unroll
        for (int j = 0; j < 8; j++) acc[i][j] = 0.f;

    for (int idx = tid; idx < 3 * 324; idx += 256) {
        int c = idx / 324, p = idx - c * 324;
        int iy = p / 18, ix = p - iy * 18;
        int gy = oy0 + iy, gx = ox0 + ix;
        float v = 0.f;
        if (gy < 128 && gx < 128) v = x[((b * 3 + c) * 128 + gy) * 128 + gx];
        xs[c][iy * 20 + ix] = v;
    }
    __syncthreads();

    auto stage = [&](int cin, int bf) {
        float a0 = w0[cin * 3 + 0], a1 = w0[cin * 3 + 1], a2 = w0[cin * 3 + 2];
        float scl = g_scale[0][cin], bia = g_bias[0][cin];
        for (int idx = tid; idx < 324; idx += 256) {
            int iy = idx / 18, ix = idx - iy * 18;
            int o = iy * 20 + ix;
            float v = xs[0][o] * a0 + xs[1][o] * a1 + xs[2][o] * a2;
            in_s[bf][o] = fmaxf(fmaf(v, scl, bia), 0.f);
        }
        for (int idx = tid; idx < 576; idx += 256) {
            int o = idx / 9, t = idx - o * 9;
            ws[bf][o * 12 + t] = w1[(o * 64 + cin) * 9 + t];
        }
    };

    stage(0, 0);
    stage(1, 1);
    __syncthreads();
    for (int cin = 0; cin < 64; cin += 2) {
        if (cin + 2 < 64) {
            stage(cin + 2, (cin + 2) & 3);
            stage(cin + 3, (cin + 3) & 3);
        }
        conv_tile_accum<8>(in_s[cin & 3], ws[cin & 3], acc, cg, ry, cx);
        conv_tile_accum<8>(in_s[(cin + 1) & 3], ws[(cin + 1) & 3], acc, cg, ry,
                           cx);
        __syncthreads();
    }

#pragma unroll
    for (int ch = 0; ch < 8; ch++) {
        const int och = cg * 8 + ch;
        float* db = g_a1 + ((size_t)(b * 64 + och)) * 126 * 126;
#pragma unroll
        for (int r = 0; r < 2; r++) {
            int oy = oy0 + ry + r;
            if (oy >= 126) continue;
#pragma unroll
            for (int c = 0; c < 4; c++) {
                int ox = ox0 + cx + c;
                if (ox < 126) db[oy * 126 + ox] = acc[ch][r * 4 + c];
            }
        }
    }
}

// generic 3x3 conv; OCB out-channels per thread, oc-split via blockIdx.z.
// Quad-buffered staging: one barrier per TWO cins.
template <int IH, int OCB>
__global__ __launch_bounds__(256, 2) void conv3x3_kernel(
    const float* __restrict__ src, const float* __restrict__ wconv,
    float* __restrict__ dst, int lidx) {
    constexpr int OH = IH - 2;
    constexpr int TX = (OH + 15) / 16;
    constexpr int NOC = 8 * OCB;
    __shared__ float in_s[4][360];
    __shared__ float ws[4][NOC * 12];
    const int b = blockIdx.y;
    const int oc0 = blockIdx.z * NOC;
    const int tx = blockIdx.x % TX, ty = blockIdx.x / TX;
    const int oy0 = ty * 16, ox0 = tx * 16;
    const int tid = threadIdx.x;
    const int cg = tid >> 5;
    const int sp = tid & 31;
    const int ry = (sp >> 2) * 2, cx = (sp & 3) * 4;

    float acc[OCB][8];
#pragma unroll
    for (int i = 0; i < OCB; i++)
#pragma unroll
        for (int j = 0; j < 8; j++) acc[i][j] = 0.f;

    auto stage = [&](int cin, int bf) {
        float scl = g_scale[lidx][cin], bia = g_bias[lidx][cin];
        const float* sb = src + ((size_t)(b * 64 + cin)) * IH * IH;
        for (int idx = tid; idx < 324; idx += 256) {
            int iy = idx / 18, ix = idx - iy * 18;
            int gy = oy0 + iy, gx = ox0 + ix;
            float v = 0.f;
            if (gy < IH && gx < IH) v = sb[gy * IH + gx];
            in_s[bf][iy * 20 + ix] = fmaxf(fmaf(v, scl, bia), 0.f);
        }
        for (int idx = tid; idx < NOC * 9; idx += 256) {
            int o = idx / 9, t = idx - o * 9;
            ws[bf][o * 12 + t] = wconv[((oc0 + o) * 64 + cin) * 9 + t];
        }
    };

    stage(0, 0);
    stage(1, 1);
    __syncthreads();
    for (int cin = 0; cin < 64; cin += 2) {
        if (cin + 2 < 64) {
            stage(cin + 2, (cin + 2) & 3);
            stage(cin + 3, (cin + 3) & 3);
        }
        conv_tile_accum<OCB>(in_s[cin & 3], ws[cin & 3], acc, cg, ry, cx);
        conv_tile_accum<OCB>(in_s[(cin + 1) & 3], ws[(cin + 1) & 3], acc, cg,
                             ry, cx);
        __syncthreads();
    }

#pragma unroll
    for (int ch = 0; ch < OCB; ch++) {
        const int och = oc0 + cg * OCB + ch;
        float* db = dst + ((size_t)(b * 64 + och)) * OH * OH;
#pragma unroll
        for (int r = 0; r < 2; r++) {
            int oy = oy0 + ry + r;
            if (oy >= OH) continue;
#pragma unroll
            for (int c = 0; c < 4; c++) {
                int ox = ox0 + cx + c;
                if (ox < OH) db[oy * OH + ox] = acc[ch][r * 4 + c];
            }
        }
    }
}

// ---------------------------------------------------------------------------
// fused maxpool(3,2) + per-channel stats; LAST BLOCK computes scale/bias for
// layer l and re-zeroes accumulators.
template <int CH, int PH>
__global__ void poolstats_kernel(const float* __restrict__ src,
                                 float* __restrict__ dst, int l,
                                 const float* __restrict__ gamma,
                                 const float* __restrict__ beta, double N) {
    __shared__ float r1[256], r2[256];
    __shared__ bool is_last;
    int bc = blockIdx.x;
    int c = bc & 63;
    const float* sb = src + (size_t)bc * CH * CH;
    float* db = dst + (size_t)bc * PH * PH;
    float s = 0.f, q = 0.f;
    for (int i = threadIdx.x; i < PH * PH; i += 256) {
        int py = i / PH, px = i - py * PH;
        const float* w = sb + (2 * py) * CH + 2 * px;
        float m = w[0];
#pragma unroll
        for (int di = 0; di < 3; di++)
#pragma unroll
            for (int dj = 0; dj < 3; dj++) m = fmaxf(m, w[di * CH + dj]);
        db[i] = m;
        s += m;
        q = fmaf(m, m, q);
    }
    r1[threadIdx.x] = s; r2[threadIdx.x] = q;
    __syncthreads();
    for (int o = 128; o > 0; o >>= 1) {
        if (threadIdx.x < o) {
            r1[threadIdx.x] += r1[threadIdx.x + o];
            r2[threadIdx.x] += r2[threadIdx.x + o];
        }
        __syncthreads();
    }
    if (threadIdx.x == 0) {
        atomicAdd(&g_dsum[c], (double)r1[0]);
        atomicAdd(&g_dsq[c], (double)r2[0]);
    }
    // last-block: scale/bias
    __threadfence();
    if (threadIdx.x == 0)
        is_last = (atomicAdd(&g_cnt1, 1) == (int)gridDim.x - 1);
    __syncthreads();
    if (!is_last) return;
    __threadfence();
    int cc = threadIdx.x;
    if (cc < 64) {
        double m = g_dsum[cc] / N;
        double var = g_dsq[cc] / N - m * m;
        double sc = (double)gamma[cc] / sqrt(var + 1e-5);
        g_scale[l][cc] = (float)sc;
        g_bias[l][cc] = (float)((double)beta[cc] - m * sc);
    }
    __syncthreads();
    if (cc < 64) { g_dsum[cc] = 0.0; g_dsq[cc] = 0.0; }
    if (cc == 0) g_cnt1 = 0;
}

// ---------------------------------------------------------------------------
// FC; LAST BLOCK runs sequential spectral normalization.
__global__ void fc_kernel(const float* __restrict__ Wreg,
                          const float* __restrict__ breg,
                          const float* __restrict__ u0,
                          const float* __restrict__ v0) {
    __shared__ float red[256];
    __shared__ bool is_last;
    int j = blockIdx.x % 6, b = blockIdx.x / 6;
    const float* pb = g_p3 + (size_t)b * 10816;
    const float* wb = Wreg + (size_t)j * 10816;
    float s = 0.f;
    for (int k = threadIdx.x; k < 10816; k += 256) {
        int c = k / 169;
        float v = fmaxf(fmaf(pb[k], g_scale[3][c], g_bias[3][c]), 0.f);
        s += v * wb[k];
    }
    red[threadIdx.x] = s;
    __syncthreads();
    for (int o = 128; o > 0; o >>= 1) {
        if (threadIdx.x < o) red[threadIdx.x] += red[threadIdx.x + o];
        __syncthreads();
    }
    if (threadIdx.x == 0) g_traw[b * 6 + j] = red[0] + breg[j];
    // last-block: spectral norm
    __threadfence();
    if (threadIdx.x == 0)
        is_last = (atomicAdd(&g_cnt2, 1) == (int)gridDim.x - 1);
    __syncthreads();
    if (!is_last) return;
    if (threadIdx.x != 0) return;
    __threadfence();
    g_cnt2 = 0;
    float u[2] = {u0[0], u0[1]};
    float v[3] = {v0[0], v0[1], v0[2]};
    for (int bb = 0; bb < 32; bb++) {
        float W[6];
#pragma unroll
        for (int i = 0; i < 6; i++) W[i] = g_traw[bb * 6 + i];
#pragma unroll
        for (int it = 0; it < 4; it++) {
            float nv[3];
#pragma unroll
            for (int jj = 0; jj < 3; jj++)
                nv[jj] = W[jj] * u[0] + W[3 + jj] * u[1];
            float n = sqrtf(nv[0] * nv[0] + nv[1] * nv[1] + nv[2] * nv[2]);
            n = fmaxf(n, 1e-12f);
#pragma unroll
            for (int jj = 0; jj < 3; jj++) v[jj] = nv[jj] / n;
            float nu0 = W[0] * v[0] + W[1] * v[1] + W[2] * v[2];
            float nu1 = W[3] * v[0] + W[4] * v[1] + W[5] * v[2];
            n = sqrtf(nu0 * nu0 + nu1 * nu1);
            n = fmaxf(n, 1e-12f);
            u[0] = nu0 / n; u[1] = nu1 / n;
        }
        float Wv0 = W[0] * v[0] + W[1] * v[1] + W[2] * v[2];
        float Wv1 = W[3] * v[0] + W[4] * v[1] + W[5] * v[2];
        float sigma = u[0] * Wv0 + u[1] * Wv1;
#pragma unroll
        for (int i = 0; i < 6; i++) g_theta[bb * 6 + i] = W[i] / sigma;
    }
}

// affine grid + reflection bilinear sample
__global__ void sample_kernel(const float* __restrict__ x,
                              float* __restrict__ out) {
    int idx = blockIdx.x * 256 + threadIdx.x;
    if (idx >= BATCH * 16384) return;
    int b = idx >> 14, p = idx & 16383;
    int h = p >> 7, w = p & 127;
    const float* th = &g_theta[b * 6];
    float xsc = (2.f * w + 1.f) / 128.f - 1.f;
    float ysc = (2.f * h + 1.f) / 128.f - 1.f;
    float gx = th[0] * xsc + th[1] * ysc + th[2];
    float gy = th[3] * xsc + th[4] * ysc + th[5];
    float ix = ((gx + 1.f) * 128.f - 1.f) * 0.5f;
    float iy = ((gy + 1.f) * 128.f - 1.f) * 0.5f;
    float r = fmodf(fabsf(ix + 0.5f), 256.f);
    ix = (r > 128.f ? 256.f - r : r) - 0.5f;
    ix = fminf(fmaxf(ix, 0.f), 127.f);
    r = fmodf(fabsf(iy + 0.5f), 256.f);
    iy = (r > 128.f ? 256.f - r : r) - 0.5f;
    iy = fminf(fmaxf(iy, 0.f), 127.f);
    float fx0 = floorf(ix), fy0 = floorf(iy);
    float wx = ix - fx0, wy = iy - fy0;
    int x0 = min(max((int)fx0, 0), 127), y0 = min(max((int)fy0, 0), 127);
    int x1 = min(x0 + 1, 127), y1 = min(y0 + 1, 127);
    float w00 = (1.f - wx) * (1.f - wy), w10 = wx * (1.f - wy);
    float w01 = (1.f - wx) * wy, w11 = wx * wy;
#pragma unroll
    for (int c = 0; c < 3; c++) {
        const float* xb = x + (size_t)(b * 3 + c) * 16384;
        float v = xb[y0 * 128 + x0] * w00 + xb[y0 * 128 + x1] * w10 +
                  xb[y1 * 128 + x0] * w01 + xb[y1 * 128 + x1] * w11;
        out[(size_t)(b * 3 + c) * 16384 + p] = v;
    }
}

// ---------------------------------------------------------------------------
extern "C" void kernel_launch(void* const* d_in, const int* in_sizes, int n_in,
                              void* d_out, int out_size) {
    const float* x     = (const float*)d_in[0];
    const float* w0    = (const float*)d_in[1];
    const float* w1    = (const float*)d_in[2];
    const float* w2    = (const float*)d_in[3];
    const float* w3    = (const float*)d_in[4];
    const float* gamma = (const float*)d_in[5];
    const float* beta  = (const float*)d_in[6];
    const float* Wreg  = (const float*)d_in[7];
    const float* breg  = (const float*)d_in[8];
    const float* u0    = (const float*)d_in[9];
    const float* v0    = (const float*)d_in[10];
    float* out = (float*)d_out;
    (void)n_in; (void)in_sizes; (void)out_size;

    float *pa1, *pp1, *pa2, *pp2, *pa3, *pp3;
    cudaGetSymbolAddress((void**)&pa1, g_a1);
    cudaGetSymbolAddress((void**)&pp1, g_p1);
    cudaGetSymbolAddress((void**)&pa2, g_a2);
    cudaGetSymbolAddress((void**)&pp2, g_p2);
    cudaGetSymbolAddress((void**)&pa3, g_a3);
    cudaGetSymbolAddress((void**)&pp3, g_p3);

    // stats(x) + fused analytic BN0
    statsx_kernel<<<512, 256>>>(x, w0, gamma, beta);

    // conv1 (direct, fused conv0+bn0+relu) -> pool+stats+bn1
    conv1_kernel<<<dim3(64, 32), 256>>>(x, w0, w1);
    poolstats_kernel<126, 62>
        <<<2048, 256>>>(pa1, pp1, 1, gamma + 64, beta + 64, 123008.0);

    // conv2 -> pool+stats+bn2
    conv3x3_kernel<62, 8><<<dim3(16, 32, 1), 256>>>(pp1, w2, pa2, 1);
    poolstats_kernel<60, 29>
        <<<2048, 256>>>(pa2, pp2, 2, gamma + 128, beta + 128, 26912.0);

    // conv3 (oc-split x2) -> pool+stats+bn3
    conv3x3_kernel<29, 4><<<dim3(4, 32, 2), 256>>>(pp2, w3, pa3, 2);
    poolstats_kernel<27, 13>
        <<<2048, 256>>>(pa3, pp3, 3, gamma + 192, beta + 192, 5408.0);

    // fc + fused spectral norm, then sampling
    fc_kernel<<<192, 256>>>(Wreg, breg, u0, v0);
    sample_kernel<<<(32 * 16384 + 255) / 256, 256>>>(x, out);
}